// round 1
// baseline (speedup 1.0000x reference)
#include <cuda_runtime.h>
#include <math.h>

// Problem constants
#define Lx  6
#define Hd  512
#define NHd 8
#define FFd 2048
#define Vd  10000
#define Bd  4
#define Sd  2048
#define DKd 64
#define Nt  (Bd*Sd)   // 8192 tokens

// ---------------- scratch (static device globals; no runtime alloc) ----------------
__device__ float g_x[Nt*Hd];     // running activations
__device__ float g_h[Nt*Hd];     // layernorm output
__device__ float g_q[Nt*Hd];
__device__ float g_k[Nt*Hd];
__device__ float g_v[Nt*Hd];
__device__ float g_ctx[Nt*Hd];
__device__ float g_ff[Nt*FFd];
__device__ float g_p[(size_t)Bd*NHd*Sd*Sd];  // 512MB attention scores/probs

// ---------------- embedding + sinusoidal positional encoding ----------------
__global__ void embed_kernel(const int* __restrict__ src,
                             const float* __restrict__ emb,
                             float* __restrict__ x)
{
    int idx = blockIdx.x * blockDim.x + threadIdx.x;
    if (idx >= Nt*Hd) return;
    int n = idx >> 9;          // / 512
    int c = idx & (Hd-1);
    int s = n & (Sd-1);        // position within sequence
    int tok = src[n];
    int i2 = c & ~1;           // 2*i
    float div = expf(-(logf(10000.0f)/(float)Hd) * (float)i2);
    float ang = (float)s * div;
    float pe = (c & 1) ? cosf(ang) : sinf(ang);
    x[idx] = emb[(size_t)tok*Hd + c] + pe;
}

// ---------------- layernorm: one block (128 thr) per row of 512 ----------------
__global__ void layernorm_kernel(const float* __restrict__ x,
                                 const float* __restrict__ g,
                                 const float* __restrict__ b,
                                 float* __restrict__ out)
{
    int row = blockIdx.x;
    int tid = threadIdx.x;              // 0..127
    const float* xr = x + (size_t)row*Hd;
    float4 v = *reinterpret_cast<const float4*>(xr + tid*4);

    __shared__ float red[4];
    __shared__ float red2[4];

    float s = v.x + v.y + v.z + v.w;
    #pragma unroll
    for (int o = 16; o > 0; o >>= 1) s += __shfl_xor_sync(0xffffffffu, s, o);
    if ((tid & 31) == 0) red[tid >> 5] = s;
    __syncthreads();
    float mean = (red[0] + red[1] + red[2] + red[3]) * (1.0f/(float)Hd);

    float dx = v.x - mean, dy = v.y - mean, dz = v.z - mean, dw = v.w - mean;
    float ss = dx*dx + dy*dy + dz*dz + dw*dw;
    #pragma unroll
    for (int o = 16; o > 0; o >>= 1) ss += __shfl_xor_sync(0xffffffffu, ss, o);
    if ((tid & 31) == 0) red2[tid >> 5] = ss;
    __syncthreads();
    float var = (red2[0] + red2[1] + red2[2] + red2[3]) * (1.0f/(float)Hd);
    float rstd = rsqrtf(var + 1e-5f);

    int c = tid*4;
    float4 gg = *reinterpret_cast<const float4*>(g + c);
    float4 bb = *reinterpret_cast<const float4*>(b + c);
    float4 o4;
    o4.x = dx*rstd*gg.x + bb.x;
    o4.y = dy*rstd*gg.y + bb.y;
    o4.z = dz*rstd*gg.z + bb.z;
    o4.w = dw*rstd*gg.w + bb.w;
    *reinterpret_cast<float4*>(out + (size_t)row*Hd + c) = o4;
}

// ---------------- main dense GEMM: C = act(A[M,K] @ W[K,N] + bias [+R]) ----------------
// 128x128x8 tile, 256 threads, 8x8 micro tile
template<bool RELU, bool RES>
__global__ void gemm128_kernel(const float* __restrict__ A,
                               const float* __restrict__ W,
                               const float* __restrict__ bias,
                               const float* __restrict__ R,
                               float* __restrict__ C,
                               int M, int N, int K)
{
    __shared__ float As[8][132];
    __shared__ float Bs[8][132];

    int tid = threadIdx.x;
    int rowBase = blockIdx.y * 128;
    int colBase = blockIdx.x * 128;

    int aRow = tid >> 1;           // 0..127
    int aCol = (tid & 1) * 4;      // 0 or 4
    int bRow = tid >> 5;           // 0..7
    int bCol = (tid & 31) * 4;     // 0..124

    int r0 = (tid >> 4) * 8;
    int c0 = (tid & 15) * 8;

    float acc[8][8];
    #pragma unroll
    for (int i = 0; i < 8; i++)
        #pragma unroll
        for (int j = 0; j < 8; j++) acc[i][j] = 0.0f;

    for (int k0 = 0; k0 < K; k0 += 8) {
        float4 av = *reinterpret_cast<const float4*>(
            &A[(size_t)(rowBase + aRow) * K + k0 + aCol]);
        As[aCol+0][aRow] = av.x;
        As[aCol+1][aRow] = av.y;
        As[aCol+2][aRow] = av.z;
        As[aCol+3][aRow] = av.w;

        int gcol = colBase + bCol;
        float4 bv = make_float4(0.f, 0.f, 0.f, 0.f);
        if (gcol < N)
            bv = *reinterpret_cast<const float4*>(
                &W[(size_t)(k0 + bRow) * N + gcol]);
        *reinterpret_cast<float4*>(&Bs[bRow][bCol]) = bv;

        __syncthreads();
        #pragma unroll
        for (int kk = 0; kk < 8; kk++) {
            float a[8], bb[8];
            *reinterpret_cast<float4*>(&a[0]) = *reinterpret_cast<float4*>(&As[kk][r0]);
            *reinterpret_cast<float4*>(&a[4]) = *reinterpret_cast<float4*>(&As[kk][r0+4]);
            *reinterpret_cast<float4*>(&bb[0]) = *reinterpret_cast<float4*>(&Bs[kk][c0]);
            *reinterpret_cast<float4*>(&bb[4]) = *reinterpret_cast<float4*>(&Bs[kk][c0+4]);
            #pragma unroll
            for (int i = 0; i < 8; i++)
                #pragma unroll
                for (int j = 0; j < 8; j++)
                    acc[i][j] = fmaf(a[i], bb[j], acc[i][j]);
        }
        __syncthreads();
    }

    #pragma unroll
    for (int i = 0; i < 8; i++) {
        int gr = rowBase + r0 + i;
        #pragma unroll
        for (int j = 0; j < 8; j++) {
            int gc = colBase + c0 + j;
            if (gc < N) {
                float val = acc[i][j] + bias[gc];
                if (RES) val += R[(size_t)gr * N + gc];
                if (RELU) val = fmaxf(val, 0.0f);
                C[(size_t)gr * N + gc] = val;
            }
        }
    }
}

// ---------------- attention scores: P[bh][i][j] = Q_i . K_j  (scale in softmax) ----------------
// grid: (S/128, S/128, B*NH); 128x128 tile, K=DK=64
__global__ void attn_scores_kernel(const float* __restrict__ q,
                                   const float* __restrict__ k,
                                   float* __restrict__ p)
{
    int bi = blockIdx.z;
    int b = bi >> 3;
    int h = bi & 7;
    const float* Q  = q + (size_t)b*Sd*Hd + h*DKd;
    const float* Km = k + (size_t)b*Sd*Hd + h*DKd;
    float* P = p + (size_t)bi*Sd*Sd;

    __shared__ float As[8][132];
    __shared__ float Bs[8][132];

    int tid = threadIdx.x;
    int rowBase = blockIdx.y * 128;
    int colBase = blockIdx.x * 128;

    int aRow = tid >> 1;           // 0..127
    int aCol = (tid & 1) * 4;      // 0 or 4
    int r0 = (tid >> 4) * 8;
    int c0 = (tid & 15) * 8;

    float acc[8][8];
    #pragma unroll
    for (int i = 0; i < 8; i++)
        #pragma unroll
        for (int j = 0; j < 8; j++) acc[i][j] = 0.0f;

    for (int k0 = 0; k0 < DKd; k0 += 8) {
        float4 av = *reinterpret_cast<const float4*>(
            &Q[(size_t)(rowBase + aRow) * Hd + k0 + aCol]);
        As[aCol+0][aRow] = av.x;
        As[aCol+1][aRow] = av.y;
        As[aCol+2][aRow] = av.z;
        As[aCol+3][aRow] = av.w;

        float4 bv = *reinterpret_cast<const float4*>(
            &Km[(size_t)(colBase + aRow) * Hd + k0 + aCol]);
        Bs[aCol+0][aRow] = bv.x;
        Bs[aCol+1][aRow] = bv.y;
        Bs[aCol+2][aRow] = bv.z;
        Bs[aCol+3][aRow] = bv.w;

        __syncthreads();
        #pragma unroll
        for (int kk = 0; kk < 8; kk++) {
            float a[8], bb[8];
            *reinterpret_cast<float4*>(&a[0]) = *reinterpret_cast<float4*>(&As[kk][r0]);
            *reinterpret_cast<float4*>(&a[4]) = *reinterpret_cast<float4*>(&As[kk][r0+4]);
            *reinterpret_cast<float4*>(&bb[0]) = *reinterpret_cast<float4*>(&Bs[kk][c0]);
            *reinterpret_cast<float4*>(&bb[4]) = *reinterpret_cast<float4*>(&Bs[kk][c0+4]);
            #pragma unroll
            for (int i = 0; i < 8; i++)
                #pragma unroll
                for (int j = 0; j < 8; j++)
                    acc[i][j] = fmaf(a[i], bb[j], acc[i][j]);
        }
        __syncthreads();
    }

    #pragma unroll
    for (int i = 0; i < 8; i++) {
        float* pr = &P[(size_t)(rowBase + r0 + i) * Sd + colBase + c0];
        float4 v0 = make_float4(acc[i][0], acc[i][1], acc[i][2], acc[i][3]);
        float4 v1 = make_float4(acc[i][4], acc[i][5], acc[i][6], acc[i][7]);
        *reinterpret_cast<float4*>(pr)     = v0;
        *reinterpret_cast<float4*>(pr + 4) = v1;
    }
}

// ---------------- softmax over rows of length S, with 1/sqrt(DK) scale and key mask ----------------
// grid = B*NH*S blocks of 256 threads, 8 elements each
__global__ void softmax_kernel(float* __restrict__ p,
                               const unsigned char* __restrict__ mask)
{
    int row = blockIdx.x;
    int bi = row >> 11;            // / S
    int b  = bi >> 3;              // / NH
    float* pr = p + (size_t)row * Sd;
    const unsigned char* mr = mask + (size_t)b * Sd;
    int tid = threadIdx.x;
    int base = tid * 8;

    float vals[8];
    float4 v0 = *reinterpret_cast<const float4*>(pr + base);
    float4 v1 = *reinterpret_cast<const float4*>(pr + base + 4);
    vals[0]=v0.x; vals[1]=v0.y; vals[2]=v0.z; vals[3]=v0.w;
    vals[4]=v1.x; vals[5]=v1.y; vals[6]=v1.z; vals[7]=v1.w;

    const float scale = 0.125f;    // 1/sqrt(64)
    float m = -3.4e38f;
    #pragma unroll
    for (int j = 0; j < 8; j++) {
        float t = vals[j] * scale;
        if (mr[base + j]) t = -1e30f;
        vals[j] = t;
        m = fmaxf(m, t);
    }

    __shared__ float sm[8];
    __shared__ float ssum[8];
    #pragma unroll
    for (int o = 16; o > 0; o >>= 1) m = fmaxf(m, __shfl_xor_sync(0xffffffffu, m, o));
    if ((tid & 31) == 0) sm[tid >> 5] = m;
    __syncthreads();
    m = sm[0];
    #pragma unroll
    for (int w = 1; w < 8; w++) m = fmaxf(m, sm[w]);

    float s = 0.0f;
    #pragma unroll
    for (int j = 0; j < 8; j++) {
        vals[j] = expf(vals[j] - m);
        s += vals[j];
    }
    #pragma unroll
    for (int o = 16; o > 0; o >>= 1) s += __shfl_xor_sync(0xffffffffu, s, o);
    if ((tid & 31) == 0) ssum[tid >> 5] = s;
    __syncthreads();
    s = ssum[0];
    #pragma unroll
    for (int w = 1; w < 8; w++) s += ssum[w];
    float inv = 1.0f / s;

    v0 = make_float4(vals[0]*inv, vals[1]*inv, vals[2]*inv, vals[3]*inv);
    v1 = make_float4(vals[4]*inv, vals[5]*inv, vals[6]*inv, vals[7]*inv);
    *reinterpret_cast<float4*>(pr + base)     = v0;
    *reinterpret_cast<float4*>(pr + base + 4) = v1;
}

// ---------------- ctx = P @ V  (per (b,h): [S,S]x[S,DK]) ----------------
// grid: (S/64, B*NH); tile 64x64, K tiles of 16, 256 thr, 4x4 micro
__global__ void attn_ctx_kernel(const float* __restrict__ p,
                                const float* __restrict__ v,
                                float* __restrict__ ctx)
{
    int bi = blockIdx.y;
    int b = bi >> 3;
    int h = bi & 7;
    const float* P = p + (size_t)bi*Sd*Sd;
    const float* V = v + (size_t)b*Sd*Hd + h*DKd;
    float* C = ctx + (size_t)b*Sd*Hd + h*DKd;

    __shared__ float As[16][68];
    __shared__ float Bs[16][68];

    int tid = threadIdx.x;
    int rowBase = blockIdx.x * 64;

    int ar = tid >> 2, ac = (tid & 3) * 4;      // A: 64 rows x 16 k
    int br = tid >> 4, bc = (tid & 15) * 4;     // B: 16 rows x 64 cols
    int r0 = (tid >> 4) * 4;
    int c0 = (tid & 15) * 4;

    float acc[4][4];
    #pragma unroll
    for (int i = 0; i < 4; i++)
        #pragma unroll
        for (int j = 0; j < 4; j++) acc[i][j] = 0.0f;

    for (int k0 = 0; k0 < Sd; k0 += 16) {
        float4 av = *reinterpret_cast<const float4*>(
            &P[(size_t)(rowBase + ar) * Sd + k0 + ac]);
        As[ac+0][ar] = av.x;
        As[ac+1][ar] = av.y;
        As[ac+2][ar] = av.z;
        As[ac+3][ar] = av.w;

        float4 bv = *reinterpret_cast<const float4*>(
            &V[(size_t)(k0 + br) * Hd + bc]);
        *reinterpret_cast<float4*>(&Bs[br][bc]) = bv;

        __syncthreads();
        #pragma unroll
        for (int kk = 0; kk < 16; kk++) {
            float4 a  = *reinterpret_cast<float4*>(&As[kk][r0]);
            float4 bb = *reinterpret_cast<float4*>(&Bs[kk][c0]);
            float aa[4] = {a.x, a.y, a.z, a.w};
            float bbv[4] = {bb.x, bb.y, bb.z, bb.w};
            #pragma unroll
            for (int i = 0; i < 4; i++)
                #pragma unroll
                for (int j = 0; j < 4; j++)
                    acc[i][j] = fmaf(aa[i], bbv[j], acc[i][j]);
        }
        __syncthreads();
    }

    #pragma unroll
    for (int i = 0; i < 4; i++) {
        float4 o4 = make_float4(acc[i][0], acc[i][1], acc[i][2], acc[i][3]);
        *reinterpret_cast<float4*>(&C[(size_t)(rowBase + r0 + i) * Hd + c0]) = o4;
    }
}

// ---------------- launch ----------------
extern "C" void kernel_launch(void* const* d_in, const int* in_sizes, int n_in,
                              void* d_out, int out_size)
{
    const int*           src  = (const int*)d_in[0];
    const unsigned char* mask = (const unsigned char*)d_in[1];
    const float* emb  = (const float*)d_in[2];
    const float* Wq   = (const float*)d_in[3];
    const float* bq   = (const float*)d_in[4];
    const float* Wk   = (const float*)d_in[5];
    const float* bk   = (const float*)d_in[6];
    const float* Wv   = (const float*)d_in[7];
    const float* bv   = (const float*)d_in[8];
    const float* Wo   = (const float*)d_in[9];
    const float* bo   = (const float*)d_in[10];
    const float* ln1g = (const float*)d_in[11];
    const float* ln1b = (const float*)d_in[12];
    const float* W1   = (const float*)d_in[13];
    const float* b1   = (const float*)d_in[14];
    const float* W2   = (const float*)d_in[15];
    const float* b2   = (const float*)d_in[16];
    const float* ln2g = (const float*)d_in[17];
    const float* ln2b = (const float*)d_in[18];
    const float* lnfg = (const float*)d_in[19];
    const float* lnfb = (const float*)d_in[20];
    const float* Wg   = (const float*)d_in[21];
    const float* bg   = (const float*)d_in[22];
    float* out = (float*)d_out;

    float *x, *h, *q, *k, *v, *ctx, *ff, *p;
    cudaGetSymbolAddress((void**)&x,   g_x);
    cudaGetSymbolAddress((void**)&h,   g_h);
    cudaGetSymbolAddress((void**)&q,   g_q);
    cudaGetSymbolAddress((void**)&k,   g_k);
    cudaGetSymbolAddress((void**)&v,   g_v);
    cudaGetSymbolAddress((void**)&ctx, g_ctx);
    cudaGetSymbolAddress((void**)&ff,  g_ff);
    cudaGetSymbolAddress((void**)&p,   g_p);

    embed_kernel<<<(Nt*Hd + 255)/256, 256>>>(src, emb, x);

    dim3 gH(Hd/128,  Nt/128);        // N=512
    dim3 gF(FFd/128, Nt/128);        // N=2048
    dim3 gV((Vd+127)/128, Nt/128);   // N=10000

    for (int l = 0; l < Lx; l++) {
        layernorm_kernel<<<Nt, 128>>>(x, ln1g + (size_t)l*Hd, ln1b + (size_t)l*Hd, h);

        gemm128_kernel<false,false><<<gH, 256>>>(h, Wq + (size_t)l*Hd*Hd, bq + (size_t)l*Hd,
                                                 nullptr, q, Nt, Hd, Hd);
        gemm128_kernel<false,false><<<gH, 256>>>(h, Wk + (size_t)l*Hd*Hd, bk + (size_t)l*Hd,
                                                 nullptr, k, Nt, Hd, Hd);
        gemm128_kernel<false,false><<<gH, 256>>>(h, Wv + (size_t)l*Hd*Hd, bv + (size_t)l*Hd,
                                                 nullptr, v, Nt, Hd, Hd);

        attn_scores_kernel<<<dim3(Sd/128, Sd/128, Bd*NHd), 256>>>(q, k, p);
        softmax_kernel<<<Bd*NHd*Sd, 256>>>(p, mask);
        attn_ctx_kernel<<<dim3(Sd/64, Bd*NHd), 256>>>(p, v, ctx);

        // x = x + ctx @ Wo + bo
        gemm128_kernel<false,true><<<gH, 256>>>(ctx, Wo + (size_t)l*Hd*Hd, bo + (size_t)l*Hd,
                                                x, x, Nt, Hd, Hd);

        layernorm_kernel<<<Nt, 128>>>(x, ln2g + (size_t)l*Hd, ln2b + (size_t)l*Hd, h);

        // ff = relu(h @ W1 + b1)
        gemm128_kernel<true,false><<<gF, 256>>>(h, W1 + (size_t)l*Hd*FFd, b1 + (size_t)l*FFd,
                                                nullptr, ff, Nt, FFd, Hd);
        // x = x + ff @ W2 + b2
        gemm128_kernel<false,true><<<gH, 256>>>(ff, W2 + (size_t)l*FFd*Hd, b2 + (size_t)l*Hd,
                                                x, x, Nt, Hd, FFd);
    }

    layernorm_kernel<<<Nt, 128>>>(x, lnfg, lnfb, h);
    gemm128_kernel<false,false><<<gV, 256>>>(h, Wg, bg, nullptr, out, Nt, Vd, Hd);
}

// round 2
// speedup vs baseline: 2.5527x; 2.5527x over previous
#include <cuda_runtime.h>
#include <math.h>

// Problem constants
#define Lx  6
#define Hd  512
#define NHd 8
#define FFd 2048
#define Vd  10000
#define Bd  4
#define Sd  2048
#define DKd 64
#define Nt  (Bd*Sd)   // 8192 tokens

// ---------------- scratch (static device globals; no runtime alloc) ----------------
__device__ float g_x[Nt*Hd];
__device__ float g_h[Nt*Hd];
__device__ float g_q[Nt*Hd];
__device__ float g_k[Nt*Hd];
__device__ float g_v[Nt*Hd];
__device__ float g_ctx[Nt*Hd];
__device__ float g_ff[Nt*FFd];
__device__ float g_p[(size_t)Bd*NHd*Sd*Sd];  // 512MB attention scores/probs

// ---------------- PTX helpers ----------------
__device__ __forceinline__ unsigned f2tf(float x) {
    unsigned r;
    asm("cvt.rna.tf32.f32 %0, %1;" : "=r"(r) : "f"(x));
    return r;
}

__device__ __forceinline__ void mma8(float* c,
                                     unsigned a0, unsigned a1, unsigned a2, unsigned a3,
                                     unsigned b0, unsigned b1) {
    asm volatile(
        "mma.sync.aligned.m16n8k8.row.col.f32.tf32.tf32.f32 "
        "{%0,%1,%2,%3}, {%4,%5,%6,%7}, {%8,%9}, {%0,%1,%2,%3};"
        : "+f"(c[0]), "+f"(c[1]), "+f"(c[2]), "+f"(c[3])
        : "r"(a0), "r"(a1), "r"(a2), "r"(a3), "r"(b0), "r"(b1));
}

__device__ __forceinline__ void cpa16(unsigned dst, const float* src) {
    asm volatile("cp.async.ca.shared.global [%0], [%1], 16;" :: "r"(dst), "l"(src));
}
__device__ __forceinline__ void cpa16p(unsigned dst, const float* src, int bytes) {
    asm volatile("cp.async.ca.shared.global [%0], [%1], 16, %2;" :: "r"(dst), "l"(src), "r"(bytes));
}
__device__ __forceinline__ void cp_commit() { asm volatile("cp.async.commit_group;"); }
template<int N> __device__ __forceinline__ void cp_wait() {
    asm volatile("cp.async.wait_group %0;" :: "n"(N));
}

// ---------------- embedding + sinusoidal positional encoding ----------------
__global__ void embed_kernel(const int* __restrict__ src,
                             const float* __restrict__ emb,
                             float* __restrict__ x)
{
    int idx = blockIdx.x * blockDim.x + threadIdx.x;
    if (idx >= Nt*Hd) return;
    int n = idx >> 9;
    int c = idx & (Hd-1);
    int s = n & (Sd-1);
    int tok = src[n];
    int i2 = c & ~1;
    float div = expf(-(logf(10000.0f)/(float)Hd) * (float)i2);
    float ang = (float)s * div;
    float pe = (c & 1) ? cosf(ang) : sinf(ang);
    x[idx] = emb[(size_t)tok*Hd + c] + pe;
}

// ---------------- layernorm: one block (128 thr) per row of 512 ----------------
__global__ void layernorm_kernel(const float* __restrict__ x,
                                 const float* __restrict__ g,
                                 const float* __restrict__ b,
                                 float* __restrict__ out)
{
    int row = blockIdx.x;
    int tid = threadIdx.x;
    const float* xr = x + (size_t)row*Hd;
    float4 v = *reinterpret_cast<const float4*>(xr + tid*4);

    __shared__ float red[4];
    __shared__ float red2[4];

    float s = v.x + v.y + v.z + v.w;
    #pragma unroll
    for (int o = 16; o > 0; o >>= 1) s += __shfl_xor_sync(0xffffffffu, s, o);
    if ((tid & 31) == 0) red[tid >> 5] = s;
    __syncthreads();
    float mean = (red[0] + red[1] + red[2] + red[3]) * (1.0f/(float)Hd);

    float dx = v.x - mean, dy = v.y - mean, dz = v.z - mean, dw = v.w - mean;
    float ss = dx*dx + dy*dy + dz*dz + dw*dw;
    #pragma unroll
    for (int o = 16; o > 0; o >>= 1) ss += __shfl_xor_sync(0xffffffffu, ss, o);
    if ((tid & 31) == 0) red2[tid >> 5] = ss;
    __syncthreads();
    float var = (red2[0] + red2[1] + red2[2] + red2[3]) * (1.0f/(float)Hd);
    float rstd = rsqrtf(var + 1e-5f);

    int c = tid*4;
    float4 gg = *reinterpret_cast<const float4*>(g + c);
    float4 bb = *reinterpret_cast<const float4*>(b + c);
    float4 o4;
    o4.x = dx*rstd*gg.x + bb.x;
    o4.y = dy*rstd*gg.y + bb.y;
    o4.z = dz*rstd*gg.z + bb.z;
    o4.w = dw*rstd*gg.w + bb.w;
    *reinterpret_cast<float4*>(out + (size_t)row*Hd + c) = o4;
}

// ============================================================================
// Dense GEMM via tf32 mma.sync: C = act(A[M,K] @ W[K,N] + bias [+R])
// 128x128 block tile, 8 warps (2x4), 64x32 warp tile, KT=16, cp.async 2-stage
// ============================================================================
template<bool RELU, bool RES>
__global__ void __launch_bounds__(256, 2)
gemm_tf32(const float* __restrict__ A,
          const float* __restrict__ W,
          const float* __restrict__ bias,
          const float* __restrict__ R,
          float* __restrict__ C,
          int M, int N, int K)
{
    __shared__ __align__(16) float As[2][128][20];   // [stage][m][k], pad 20
    __shared__ __align__(16) float Bs[2][16][132];   // [stage][k][n], pad 132

    int tid = threadIdx.x;
    int wid = tid >> 5, lane = tid & 31;
    int g = lane >> 2, t = lane & 3;
    int wm = (wid >> 2) * 64;
    int wn = (wid & 3) * 32;
    int rowBase = blockIdx.y * 128;
    int colBase = blockIdx.x * 128;

    float acc[4][4][4];
    #pragma unroll
    for (int mi = 0; mi < 4; mi++)
        #pragma unroll
        for (int ni = 0; ni < 4; ni++)
            #pragma unroll
            for (int r = 0; r < 4; r++) acc[mi][ni][r] = 0.0f;

    int nstages = K >> 4;

    // ---- stage loader ----
    auto loadStage = [&](int st, int k0) {
        #pragma unroll
        for (int i = 0; i < 2; i++) {
            int li = tid + i * 256;
            int r = li >> 2, kq = (li & 3) * 4;
            unsigned d = (unsigned)__cvta_generic_to_shared(&As[st][r][kq]);
            cpa16(d, &A[(size_t)(rowBase + r) * K + k0 + kq]);
        }
        #pragma unroll
        for (int i = 0; i < 2; i++) {
            int li = tid + i * 256;
            int r = li >> 5, cq = (li & 31) * 4;
            unsigned d = (unsigned)__cvta_generic_to_shared(&Bs[st][r][cq]);
            int gc = colBase + cq;
            cpa16p(d, &W[(size_t)(k0 + r) * N + gc], (gc + 4 <= N) ? 16 : 0);
        }
        cp_commit();
    };

    auto computeStage = [&](int st) {
        #pragma unroll
        for (int kk = 0; kk < 16; kk += 8) {
            unsigned a[4][4], b[4][2];
            #pragma unroll
            for (int mi = 0; mi < 4; mi++) {
                int m = wm + mi * 16 + g;
                a[mi][0] = f2tf(As[st][m    ][kk + t]);
                a[mi][1] = f2tf(As[st][m + 8][kk + t]);
                a[mi][2] = f2tf(As[st][m    ][kk + 4 + t]);
                a[mi][3] = f2tf(As[st][m + 8][kk + 4 + t]);
            }
            #pragma unroll
            for (int ni = 0; ni < 4; ni++) {
                int n = wn + ni * 8 + g;
                b[ni][0] = f2tf(Bs[st][kk + t    ][n]);
                b[ni][1] = f2tf(Bs[st][kk + 4 + t][n]);
            }
            #pragma unroll
            for (int mi = 0; mi < 4; mi++)
                #pragma unroll
                for (int ni = 0; ni < 4; ni++)
                    mma8(acc[mi][ni], a[mi][0], a[mi][1], a[mi][2], a[mi][3],
                         b[ni][0], b[ni][1]);
        }
    };

    loadStage(0, 0);
    for (int s = 0; s < nstages; s++) {
        if (s + 1 < nstages) {
            loadStage((s + 1) & 1, (s + 1) * 16);
            cp_wait<1>();
        } else {
            cp_wait<0>();
        }
        __syncthreads();
        computeStage(s & 1);
        __syncthreads();
    }

    // ---- epilogue ----
    #pragma unroll
    for (int mi = 0; mi < 4; mi++) {
        #pragma unroll
        for (int ni = 0; ni < 4; ni++) {
            int r0 = rowBase + wm + mi * 16 + g;
            int c0 = colBase + wn + ni * 8 + 2 * t;
            if (c0 < N) {
                float bx = bias[c0], by = bias[c0 + 1];
                float2 v0, v1;
                v0.x = acc[mi][ni][0] + bx;
                v0.y = acc[mi][ni][1] + by;
                v1.x = acc[mi][ni][2] + bx;
                v1.y = acc[mi][ni][3] + by;
                if (RES) {
                    float2 ra = *(const float2*)&R[(size_t)r0 * N + c0];
                    float2 rb = *(const float2*)&R[(size_t)(r0 + 8) * N + c0];
                    v0.x += ra.x; v0.y += ra.y;
                    v1.x += rb.x; v1.y += rb.y;
                }
                if (RELU) {
                    v0.x = fmaxf(v0.x, 0.f); v0.y = fmaxf(v0.y, 0.f);
                    v1.x = fmaxf(v1.x, 0.f); v1.y = fmaxf(v1.y, 0.f);
                }
                *(float2*)&C[(size_t)r0 * N + c0] = v0;
                *(float2*)&C[(size_t)(r0 + 8) * N + c0] = v1;
            }
        }
    }
}

// ============================================================================
// Attention scores via tf32 mma: P[bh][i][j] = Q_i . K_j   (scale in softmax)
// 128x128 tile, K=64 in two 32-chunks (single-buffered), Q:[m][k], K:[n][k]
// ============================================================================
__global__ void __launch_bounds__(256)
attn_scores_tf32(const float* __restrict__ q,
                 const float* __restrict__ k,
                 float* __restrict__ p)
{
    __shared__ __align__(16) float Qs[128][36];
    __shared__ __align__(16) float Ks[128][36];

    int bi = blockIdx.z;
    int b = bi >> 3, h = bi & 7;
    const float* Q  = q + (size_t)b*Sd*Hd + h*DKd;
    const float* Km = k + (size_t)b*Sd*Hd + h*DKd;
    float* P = p + (size_t)bi*Sd*Sd;

    int tid = threadIdx.x;
    int wid = tid >> 5, lane = tid & 31;
    int g = lane >> 2, t = lane & 3;
    int wm = (wid >> 2) * 64;
    int wn = (wid & 3) * 32;
    int rowBase = blockIdx.y * 128;
    int colBase = blockIdx.x * 128;

    float acc[4][4][4];
    #pragma unroll
    for (int mi = 0; mi < 4; mi++)
        #pragma unroll
        for (int ni = 0; ni < 4; ni++)
            #pragma unroll
            for (int r = 0; r < 4; r++) acc[mi][ni][r] = 0.0f;

    for (int k0 = 0; k0 < DKd; k0 += 32) {
        __syncthreads();
        #pragma unroll
        for (int i = 0; i < 4; i++) {
            int li = tid + i * 256;
            int r = li >> 3, kq = (li & 7) * 4;
            *(float4*)&Qs[r][kq] = *(const float4*)&Q[(size_t)(rowBase + r) * Hd + k0 + kq];
            *(float4*)&Ks[r][kq] = *(const float4*)&Km[(size_t)(colBase + r) * Hd + k0 + kq];
        }
        __syncthreads();

        #pragma unroll
        for (int kk = 0; kk < 32; kk += 8) {
            unsigned a[4][4], bb[4][2];
            #pragma unroll
            for (int mi = 0; mi < 4; mi++) {
                int m = wm + mi * 16 + g;
                a[mi][0] = f2tf(Qs[m    ][kk + t]);
                a[mi][1] = f2tf(Qs[m + 8][kk + t]);
                a[mi][2] = f2tf(Qs[m    ][kk + 4 + t]);
                a[mi][3] = f2tf(Qs[m + 8][kk + 4 + t]);
            }
            #pragma unroll
            for (int ni = 0; ni < 4; ni++) {
                int n = wn + ni * 8 + g;
                bb[ni][0] = f2tf(Ks[n][kk + t]);
                bb[ni][1] = f2tf(Ks[n][kk + 4 + t]);
            }
            #pragma unroll
            for (int mi = 0; mi < 4; mi++)
                #pragma unroll
                for (int ni = 0; ni < 4; ni++)
                    mma8(acc[mi][ni], a[mi][0], a[mi][1], a[mi][2], a[mi][3],
                         bb[ni][0], bb[ni][1]);
        }
    }

    #pragma unroll
    for (int mi = 0; mi < 4; mi++) {
        #pragma unroll
        for (int ni = 0; ni < 4; ni++) {
            int r0 = rowBase + wm + mi * 16 + g;
            int c0 = colBase + wn + ni * 8 + 2 * t;
            float2 v0 = make_float2(acc[mi][ni][0], acc[mi][ni][1]);
            float2 v1 = make_float2(acc[mi][ni][2], acc[mi][ni][3]);
            *(float2*)&P[(size_t)r0 * Sd + c0] = v0;
            *(float2*)&P[(size_t)(r0 + 8) * Sd + c0] = v1;
        }
    }
}

// ---------------- softmax over rows of length S, scale + key mask ----------------
__global__ void softmax_kernel(float* __restrict__ p,
                               const unsigned char* __restrict__ mask)
{
    int row = blockIdx.x;
    int bi = row >> 11;
    int b  = bi >> 3;
    float* pr = p + (size_t)row * Sd;
    const unsigned char* mr = mask + (size_t)b * Sd;
    int tid = threadIdx.x;
    int base = tid * 8;

    float vals[8];
    float4 v0 = *reinterpret_cast<const float4*>(pr + base);
    float4 v1 = *reinterpret_cast<const float4*>(pr + base + 4);
    vals[0]=v0.x; vals[1]=v0.y; vals[2]=v0.z; vals[3]=v0.w;
    vals[4]=v1.x; vals[5]=v1.y; vals[6]=v1.z; vals[7]=v1.w;

    const float scale = 0.125f;
    float m = -3.4e38f;
    #pragma unroll
    for (int j = 0; j < 8; j++) {
        float tv = vals[j] * scale;
        if (mr[base + j]) tv = -1e30f;
        vals[j] = tv;
        m = fmaxf(m, tv);
    }

    __shared__ float sm[8];
    __shared__ float ssum[8];
    #pragma unroll
    for (int o = 16; o > 0; o >>= 1) m = fmaxf(m, __shfl_xor_sync(0xffffffffu, m, o));
    if ((tid & 31) == 0) sm[tid >> 5] = m;
    __syncthreads();
    m = sm[0];
    #pragma unroll
    for (int w = 1; w < 8; w++) m = fmaxf(m, sm[w]);

    float s = 0.0f;
    #pragma unroll
    for (int j = 0; j < 8; j++) {
        vals[j] = expf(vals[j] - m);
        s += vals[j];
    }
    #pragma unroll
    for (int o = 16; o > 0; o >>= 1) s += __shfl_xor_sync(0xffffffffu, s, o);
    if ((tid & 31) == 0) ssum[tid >> 5] = s;
    __syncthreads();
    s = ssum[0];
    #pragma unroll
    for (int w = 1; w < 8; w++) s += ssum[w];
    float inv = 1.0f / s;

    v0 = make_float4(vals[0]*inv, vals[1]*inv, vals[2]*inv, vals[3]*inv);
    v1 = make_float4(vals[4]*inv, vals[5]*inv, vals[6]*inv, vals[7]*inv);
    *reinterpret_cast<float4*>(pr + base)     = v0;
    *reinterpret_cast<float4*>(pr + base + 4) = v1;
}

// ============================================================================
// ctx = P @ V via tf32 mma. Block 128(m)x64(n), 4 warps 2x2, KT=16 cp.async
// ============================================================================
__global__ void __launch_bounds__(128)
attn_pv_tf32(const float* __restrict__ p,
             const float* __restrict__ v,
             float* __restrict__ ctx)
{
    __shared__ __align__(16) float Ps[2][128][20];
    __shared__ __align__(16) float Vs[2][16][68];

    int bi = blockIdx.y;
    int b = bi >> 3, h = bi & 7;
    const float* P = p + (size_t)bi*Sd*Sd;
    const float* V = v + (size_t)b*Sd*Hd + h*DKd;
    float* C = ctx + (size_t)b*Sd*Hd + h*DKd;

    int tid = threadIdx.x;
    int wid = tid >> 5, lane = tid & 31;
    int g = lane >> 2, t = lane & 3;
    int wm = (wid >> 1) * 64;
    int wn = (wid & 1) * 32;
    int rowBase = blockIdx.x * 128;

    float acc[4][4][4];
    #pragma unroll
    for (int mi = 0; mi < 4; mi++)
        #pragma unroll
        for (int ni = 0; ni < 4; ni++)
            #pragma unroll
            for (int r = 0; r < 4; r++) acc[mi][ni][r] = 0.0f;

    auto loadStage = [&](int st, int k0) {
        #pragma unroll
        for (int i = 0; i < 4; i++) {
            int li = tid + i * 128;
            int r = li >> 2, kq = (li & 3) * 4;
            unsigned d = (unsigned)__cvta_generic_to_shared(&Ps[st][r][kq]);
            cpa16(d, &P[(size_t)(rowBase + r) * Sd + k0 + kq]);
        }
        #pragma unroll
        for (int i = 0; i < 2; i++) {
            int li = tid + i * 128;
            int r = li >> 4, cq = (li & 15) * 4;
            unsigned d = (unsigned)__cvta_generic_to_shared(&Vs[st][r][cq]);
            cpa16(d, &V[(size_t)(k0 + r) * Hd + cq]);
        }
        cp_commit();
    };

    auto computeStage = [&](int st) {
        #pragma unroll
        for (int kk = 0; kk < 16; kk += 8) {
            unsigned a[4][4], bb[4][2];
            #pragma unroll
            for (int mi = 0; mi < 4; mi++) {
                int m = wm + mi * 16 + g;
                a[mi][0] = f2tf(Ps[st][m    ][kk + t]);
                a[mi][1] = f2tf(Ps[st][m + 8][kk + t]);
                a[mi][2] = f2tf(Ps[st][m    ][kk + 4 + t]);
                a[mi][3] = f2tf(Ps[st][m + 8][kk + 4 + t]);
            }
            #pragma unroll
            for (int ni = 0; ni < 4; ni++) {
                int n = wn + ni * 8 + g;
                bb[ni][0] = f2tf(Vs[st][kk + t    ][n]);
                bb[ni][1] = f2tf(Vs[st][kk + 4 + t][n]);
            }
            #pragma unroll
            for (int mi = 0; mi < 4; mi++)
                #pragma unroll
                for (int ni = 0; ni < 4; ni++)
                    mma8(acc[mi][ni], a[mi][0], a[mi][1], a[mi][2], a[mi][3],
                         bb[ni][0], bb[ni][1]);
        }
    };

    const int nstages = Sd / 16;  // 128
    loadStage(0, 0);
    for (int s = 0; s < nstages; s++) {
        if (s + 1 < nstages) {
            loadStage((s + 1) & 1, (s + 1) * 16);
            cp_wait<1>();
        } else {
            cp_wait<0>();
        }
        __syncthreads();
        computeStage(s & 1);
        __syncthreads();
    }

    #pragma unroll
    for (int mi = 0; mi < 4; mi++) {
        #pragma unroll
        for (int ni = 0; ni < 4; ni++) {
            int r0 = rowBase + wm + mi * 16 + g;
            int c0 = wn + ni * 8 + 2 * t;
            float2 v0 = make_float2(acc[mi][ni][0], acc[mi][ni][1]);
            float2 v1 = make_float2(acc[mi][ni][2], acc[mi][ni][3]);
            *(float2*)&C[(size_t)r0 * Hd + c0] = v0;
            *(float2*)&C[(size_t)(r0 + 8) * Hd + c0] = v1;
        }
    }
}

// ---------------- launch ----------------
extern "C" void kernel_launch(void* const* d_in, const int* in_sizes, int n_in,
                              void* d_out, int out_size)
{
    const int*           src  = (const int*)d_in[0];
    const unsigned char* mask = (const unsigned char*)d_in[1];
    const float* emb  = (const float*)d_in[2];
    const float* Wq   = (const float*)d_in[3];
    const float* bq   = (const float*)d_in[4];
    const float* Wk   = (const float*)d_in[5];
    const float* bk   = (const float*)d_in[6];
    const float* Wv   = (const float*)d_in[7];
    const float* bv   = (const float*)d_in[8];
    const float* Wo   = (const float*)d_in[9];
    const float* bo   = (const float*)d_in[10];
    const float* ln1g = (const float*)d_in[11];
    const float* ln1b = (const float*)d_in[12];
    const float* W1   = (const float*)d_in[13];
    const float* b1   = (const float*)d_in[14];
    const float* W2   = (const float*)d_in[15];
    const float* b2   = (const float*)d_in[16];
    const float* ln2g = (const float*)d_in[17];
    const float* ln2b = (const float*)d_in[18];
    const float* lnfg = (const float*)d_in[19];
    const float* lnfb = (const float*)d_in[20];
    const float* Wg   = (const float*)d_in[21];
    const float* bg   = (const float*)d_in[22];
    float* out = (float*)d_out;

    float *x, *h, *q, *k, *v, *ctx, *ff, *p;
    cudaGetSymbolAddress((void**)&x,   g_x);
    cudaGetSymbolAddress((void**)&h,   g_h);
    cudaGetSymbolAddress((void**)&q,   g_q);
    cudaGetSymbolAddress((void**)&k,   g_k);
    cudaGetSymbolAddress((void**)&v,   g_v);
    cudaGetSymbolAddress((void**)&ctx, g_ctx);
    cudaGetSymbolAddress((void**)&ff,  g_ff);
    cudaGetSymbolAddress((void**)&p,   g_p);

    embed_kernel<<<(Nt*Hd + 255)/256, 256>>>(src, emb, x);

    dim3 gH(Hd/128,  Nt/128);          // N=512
    dim3 gF(FFd/128, Nt/128);          // N=2048
    dim3 gV((Vd+127)/128, Nt/128);     // N=10000 -> 79 col tiles

    for (int l = 0; l < Lx; l++) {
        layernorm_kernel<<<Nt, 128>>>(x, ln1g + (size_t)l*Hd, ln1b + (size_t)l*Hd, h);

        gemm_tf32<false,false><<<gH, 256>>>(h, Wq + (size_t)l*Hd*Hd, bq + (size_t)l*Hd,
                                            nullptr, q, Nt, Hd, Hd);
        gemm_tf32<false,false><<<gH, 256>>>(h, Wk + (size_t)l*Hd*Hd, bk + (size_t)l*Hd,
                                            nullptr, k, Nt, Hd, Hd);
        gemm_tf32<false,false><<<gH, 256>>>(h, Wv + (size_t)l*Hd*Hd, bv + (size_t)l*Hd,
                                            nullptr, v, Nt, Hd, Hd);

        attn_scores_tf32<<<dim3(Sd/128, Sd/128, Bd*NHd), 256>>>(q, k, p);
        softmax_kernel<<<Bd*NHd*Sd, 256>>>(p, mask);
        attn_pv_tf32<<<dim3(Sd/128, Bd*NHd), 128>>>(p, v, ctx);

        // x = x + ctx @ Wo + bo
        gemm_tf32<false,true><<<gH, 256>>>(ctx, Wo + (size_t)l*Hd*Hd, bo + (size_t)l*Hd,
                                           x, x, Nt, Hd, Hd);

        layernorm_kernel<<<Nt, 128>>>(x, ln2g + (size_t)l*Hd, ln2b + (size_t)l*Hd, h);

        // ff = relu(h @ W1 + b1)
        gemm_tf32<true,false><<<gF, 256>>>(h, W1 + (size_t)l*Hd*FFd, b1 + (size_t)l*FFd,
                                           nullptr, ff, Nt, FFd, Hd);
        // x = x + ff @ W2 + b2
        gemm_tf32<false,true><<<gH, 256>>>(ff, W2 + (size_t)l*FFd*Hd, b2 + (size_t)l*Hd,
                                           x, x, Nt, Hd, FFd);
    }

    layernorm_kernel<<<Nt, 128>>>(x, lnfg, lnfb, h);
    gemm_tf32<false,false><<<gV, 256>>>(h, Wg, bg, nullptr, out, Nt, Vd, Hd);
}

// round 4
// speedup vs baseline: 3.1663x; 1.2404x over previous
#include <cuda_runtime.h>
#include <math.h>

// Problem constants
#define Lx  6
#define Hd  512
#define NHd 8
#define FFd 2048
#define Vocab 10000
#define Bd  4
#define Sd  2048
#define DKd 64
#define Nt  (Bd*Sd)   // 8192 tokens

// ---------------- scratch (static device globals; no runtime alloc) ----------------
__device__ float g_x[Nt*Hd];
__device__ float g_h[Nt*Hd];
__device__ float g_q[Nt*Hd];
__device__ float g_k[Nt*Hd];
__device__ float g_v[Nt*Hd];
__device__ float g_ctx[Nt*Hd];
__device__ float g_ff[Nt*FFd];

// ---------------- PTX helpers ----------------
__device__ __forceinline__ unsigned f2tf(float x) {
    unsigned r;
    asm("cvt.rna.tf32.f32 %0, %1;" : "=r"(r) : "f"(x));
    return r;
}

__device__ __forceinline__ void mma8(float* c,
                                     unsigned a0, unsigned a1, unsigned a2, unsigned a3,
                                     unsigned b0, unsigned b1) {
    asm volatile(
        "mma.sync.aligned.m16n8k8.row.col.f32.tf32.tf32.f32 "
        "{%0,%1,%2,%3}, {%4,%5,%6,%7}, {%8,%9}, {%0,%1,%2,%3};"
        : "+f"(c[0]), "+f"(c[1]), "+f"(c[2]), "+f"(c[3])
        : "r"(a0), "r"(a1), "r"(a2), "r"(a3), "r"(b0), "r"(b1));
}

__device__ __forceinline__ void cpa16(unsigned dst, const float* src) {
    asm volatile("cp.async.ca.shared.global [%0], [%1], 16;" :: "r"(dst), "l"(src));
}
__device__ __forceinline__ void cpa16p(unsigned dst, const float* src, int bytes) {
    asm volatile("cp.async.ca.shared.global [%0], [%1], 16, %2;" :: "r"(dst), "l"(src), "r"(bytes));
}
__device__ __forceinline__ void cp_commit() { asm volatile("cp.async.commit_group;"); }
template<int N> __device__ __forceinline__ void cp_wait() {
    asm volatile("cp.async.wait_group %0;" :: "n"(N));
}

// ---------------- embedding + sinusoidal positional encoding ----------------
__global__ void embed_kernel(const int* __restrict__ src,
                             const float* __restrict__ emb,
                             float* __restrict__ x)
{
    int idx = blockIdx.x * blockDim.x + threadIdx.x;
    if (idx >= Nt*Hd) return;
    int n = idx >> 9;
    int c = idx & (Hd-1);
    int s = n & (Sd-1);
    int tok = src[n];
    int i2 = c & ~1;
    float div = expf(-(logf(10000.0f)/(float)Hd) * (float)i2);
    float ang = (float)s * div;
    float pe = (c & 1) ? cosf(ang) : sinf(ang);
    x[idx] = emb[(size_t)tok*Hd + c] + pe;
}

// ---------------- layernorm: one block (128 thr) per row of 512 ----------------
__global__ void layernorm_kernel(const float* __restrict__ x,
                                 const float* __restrict__ g,
                                 const float* __restrict__ b,
                                 float* __restrict__ out)
{
    int row = blockIdx.x;
    int tid = threadIdx.x;
    const float* xr = x + (size_t)row*Hd;
    float4 v = *reinterpret_cast<const float4*>(xr + tid*4);

    __shared__ float red[4];
    __shared__ float red2[4];

    float s = v.x + v.y + v.z + v.w;
    #pragma unroll
    for (int o = 16; o > 0; o >>= 1) s += __shfl_xor_sync(0xffffffffu, s, o);
    if ((tid & 31) == 0) red[tid >> 5] = s;
    __syncthreads();
    float mean = (red[0] + red[1] + red[2] + red[3]) * (1.0f/(float)Hd);

    float dx = v.x - mean, dy = v.y - mean, dz = v.z - mean, dw = v.w - mean;
    float ss = dx*dx + dy*dy + dz*dz + dw*dw;
    #pragma unroll
    for (int o = 16; o > 0; o >>= 1) ss += __shfl_xor_sync(0xffffffffu, ss, o);
    if ((tid & 31) == 0) red2[tid >> 5] = ss;
    __syncthreads();
    float var = (red2[0] + red2[1] + red2[2] + red2[3]) * (1.0f/(float)Hd);
    float rstd = rsqrtf(var + 1e-5f);

    int c = tid*4;
    float4 gg = *reinterpret_cast<const float4*>(g + c);
    float4 bb = *reinterpret_cast<const float4*>(b + c);
    float4 o4;
    o4.x = dx*rstd*gg.x + bb.x;
    o4.y = dy*rstd*gg.y + bb.y;
    o4.z = dz*rstd*gg.z + bb.z;
    o4.w = dw*rstd*gg.w + bb.w;
    *reinterpret_cast<float4*>(out + (size_t)row*Hd + c) = o4;
}

// ============================================================================
// Dense GEMM via tf32 mma.sync
// ============================================================================
template<bool RELU, bool RES>
__global__ void __launch_bounds__(256, 2)
gemm_tf32(const float* __restrict__ A,
          const float* __restrict__ W,
          const float* __restrict__ bias,
          const float* __restrict__ R,
          float* __restrict__ C,
          int M, int N, int K)
{
    __shared__ __align__(16) float As[2][128][20];
    __shared__ __align__(16) float Bs[2][16][132];

    int tid = threadIdx.x;
    int wid = tid >> 5, lane = tid & 31;
    int g = lane >> 2, t = lane & 3;
    int wm = (wid >> 2) * 64;
    int wn = (wid & 3) * 32;
    int rowBase = blockIdx.y * 128;
    int colBase = blockIdx.x * 128;

    float acc[4][4][4];
    #pragma unroll
    for (int mi = 0; mi < 4; mi++)
        #pragma unroll
        for (int ni = 0; ni < 4; ni++)
            #pragma unroll
            for (int r = 0; r < 4; r++) acc[mi][ni][r] = 0.0f;

    int nstages = K >> 4;

    auto loadStage = [&](int st, int k0) {
        #pragma unroll
        for (int i = 0; i < 2; i++) {
            int li = tid + i * 256;
            int r = li >> 2, kq = (li & 3) * 4;
            unsigned d = (unsigned)__cvta_generic_to_shared(&As[st][r][kq]);
            cpa16(d, &A[(size_t)(rowBase + r) * K + k0 + kq]);
        }
        #pragma unroll
        for (int i = 0; i < 2; i++) {
            int li = tid + i * 256;
            int r = li >> 5, cq = (li & 31) * 4;
            unsigned d = (unsigned)__cvta_generic_to_shared(&Bs[st][r][cq]);
            int gc = colBase + cq;
            cpa16p(d, &W[(size_t)(k0 + r) * N + gc], (gc + 4 <= N) ? 16 : 0);
        }
        cp_commit();
    };

    auto computeStage = [&](int st) {
        #pragma unroll
        for (int kk = 0; kk < 16; kk += 8) {
            unsigned a[4][4], b[4][2];
            #pragma unroll
            for (int mi = 0; mi < 4; mi++) {
                int m = wm + mi * 16 + g;
                a[mi][0] = f2tf(As[st][m    ][kk + t]);
                a[mi][1] = f2tf(As[st][m + 8][kk + t]);
                a[mi][2] = f2tf(As[st][m    ][kk + 4 + t]);
                a[mi][3] = f2tf(As[st][m + 8][kk + 4 + t]);
            }
            #pragma unroll
            for (int ni = 0; ni < 4; ni++) {
                int n = wn + ni * 8 + g;
                b[ni][0] = f2tf(Bs[st][kk + t    ][n]);
                b[ni][1] = f2tf(Bs[st][kk + 4 + t][n]);
            }
            #pragma unroll
            for (int mi = 0; mi < 4; mi++)
                #pragma unroll
                for (int ni = 0; ni < 4; ni++)
                    mma8(acc[mi][ni], a[mi][0], a[mi][1], a[mi][2], a[mi][3],
                         b[ni][0], b[ni][1]);
        }
    };

    loadStage(0, 0);
    for (int s = 0; s < nstages; s++) {
        if (s + 1 < nstages) {
            loadStage((s + 1) & 1, (s + 1) * 16);
            cp_wait<1>();
        } else {
            cp_wait<0>();
        }
        __syncthreads();
        computeStage(s & 1);
        __syncthreads();
    }

    #pragma unroll
    for (int mi = 0; mi < 4; mi++) {
        #pragma unroll
        for (int ni = 0; ni < 4; ni++) {
            int r0 = rowBase + wm + mi * 16 + g;
            int c0 = colBase + wn + ni * 8 + 2 * t;
            if (c0 < N) {
                float bx = bias[c0], by = bias[c0 + 1];
                float2 v0, v1;
                v0.x = acc[mi][ni][0] + bx;
                v0.y = acc[mi][ni][1] + by;
                v1.x = acc[mi][ni][2] + bx;
                v1.y = acc[mi][ni][3] + by;
                if (RES) {
                    float2 ra = *(const float2*)&R[(size_t)r0 * N + c0];
                    float2 rb = *(const float2*)&R[(size_t)(r0 + 8) * N + c0];
                    v0.x += ra.x; v0.y += ra.y;
                    v1.x += rb.x; v1.y += rb.y;
                }
                if (RELU) {
                    v0.x = fmaxf(v0.x, 0.f); v0.y = fmaxf(v0.y, 0.f);
                    v1.x = fmaxf(v1.x, 0.f); v1.y = fmaxf(v1.y, 0.f);
                }
                *(float2*)&C[(size_t)r0 * N + c0] = v0;
                *(float2*)&C[(size_t)(r0 + 8) * N + c0] = v1;
            }
        }
    }
}

// ============================================================================
// Flash attention: fused QK^T -> online softmax -> PV, no score materialization
// Block: 128 q-rows, 8 warps (16 rows each). K/V tiles 128x64 double-buffered.
// ============================================================================
#define KSP 68
#define VSP 72
#define PSP 132
#define FLASH_SMEM ((2*128*KSP + 2*128*VSP + 128*PSP) * 4 + 256)

__global__ void __launch_bounds__(256, 1)
flash_attn(const float* __restrict__ q,
           const float* __restrict__ k,
           const float* __restrict__ v,
           const unsigned char* __restrict__ mask,
           float* __restrict__ ctx)
{
    extern __shared__ char smem_raw[];
    float* Ks = (float*)smem_raw;                         // 2*128*KSP
    float* Vs = Ks + 2*128*KSP;                           // 2*128*VSP
    unsigned* Ps = (unsigned*)(Vs + 2*128*VSP);           // 128*PSP
    unsigned char* Ms = (unsigned char*)(Ps + 128*PSP);   // 2*128

    int bi = blockIdx.y;
    int b = bi >> 3, h = bi & 7;
    int qBase = blockIdx.x * 128;
    const float* Qg = q + (size_t)b*Sd*Hd + h*DKd;
    const float* Kg = k + (size_t)b*Sd*Hd + h*DKd;
    const float* Vg = v + (size_t)b*Sd*Hd + h*DKd;
    const unsigned char* mr = mask + (size_t)b*Sd;
    float* Cg = ctx + (size_t)b*Sd*Hd + h*DKd;

    int tid = threadIdx.x;
    int wid = tid >> 5, lane = tid & 31;
    int g = lane >> 2, t = lane & 3;
    int wm = wid * 16;

    // Q fragments in registers, pre-scaled by 1/sqrt(DK)
    unsigned qf[8][4];
    {
        int r0 = qBase + wm + g, r1 = r0 + 8;
        #pragma unroll
        for (int kk = 0; kk < 8; kk++) {
            qf[kk][0] = f2tf(0.125f * Qg[(size_t)r0*Hd + kk*8 + t]);
            qf[kk][1] = f2tf(0.125f * Qg[(size_t)r1*Hd + kk*8 + t]);
            qf[kk][2] = f2tf(0.125f * Qg[(size_t)r0*Hd + kk*8 + 4 + t]);
            qf[kk][3] = f2tf(0.125f * Qg[(size_t)r1*Hd + kk*8 + 4 + t]);
        }
    }

    float m0 = -1e30f, m1 = -1e30f, l0 = 0.f, l1 = 0.f;
    float o[8][4];
    #pragma unroll
    for (int i = 0; i < 8; i++)
        #pragma unroll
        for (int r = 0; r < 4; r++) o[i][r] = 0.f;

    auto loadTile = [&](int kt, int buf) {
        float* Ktile = Ks + buf*128*KSP;
        float* Vtile = Vs + buf*128*VSP;
        #pragma unroll
        for (int i = 0; i < 8; i++) {
            int li = tid + i * 256;
            int r = li >> 4, cq = (li & 15) * 4;
            cpa16((unsigned)__cvta_generic_to_shared(&Ktile[r*KSP + cq]),
                  &Kg[(size_t)(kt*128 + r)*Hd + cq]);
            cpa16((unsigned)__cvta_generic_to_shared(&Vtile[r*VSP + cq]),
                  &Vg[(size_t)(kt*128 + r)*Hd + cq]);
        }
        if (tid < 32) {
            uchar4 mv = *(const uchar4*)&mr[kt*128 + tid*4];
            *(uchar4*)&Ms[buf*128 + tid*4] = mv;
        }
        cp_commit();
    };

    const int NT = Sd / 128;   // 16
    loadTile(0, 0);

    for (int kt = 0; kt < NT; kt++) {
        int buf = kt & 1;
        if (kt + 1 < NT) { loadTile(kt + 1, buf ^ 1); cp_wait<1>(); }
        else             { cp_wait<0>(); }
        __syncthreads();

        const float* Ktile = Ks + buf*128*KSP;
        const float* Vtile = Vs + buf*128*VSP;
        const unsigned char* Mt = Ms + buf*128;

        // ---- S = Q K^T : 16 rows x 128 keys per warp ----
        float s[16][4];
        #pragma unroll
        for (int ni = 0; ni < 16; ni++)
            #pragma unroll
            for (int r = 0; r < 4; r++) s[ni][r] = 0.f;

        #pragma unroll
        for (int kk = 0; kk < 8; kk++) {
            #pragma unroll
            for (int ni = 0; ni < 16; ni++) {
                int n = ni*8 + g;
                unsigned b0 = f2tf(Ktile[n*KSP + kk*8 + t]);
                unsigned b1 = f2tf(Ktile[n*KSP + kk*8 + 4 + t]);
                mma8(s[ni], qf[kk][0], qf[kk][1], qf[kk][2], qf[kk][3], b0, b1);
            }
        }

        // ---- mask + row max ----
        float mt0 = -1e30f, mt1 = -1e30f;
        #pragma unroll
        for (int ni = 0; ni < 16; ni++) {
            int c = ni*8 + 2*t;
            if (Mt[c])     { s[ni][0] = -1e30f; s[ni][2] = -1e30f; }
            if (Mt[c + 1]) { s[ni][1] = -1e30f; s[ni][3] = -1e30f; }
            mt0 = fmaxf(mt0, fmaxf(s[ni][0], s[ni][1]));
            mt1 = fmaxf(mt1, fmaxf(s[ni][2], s[ni][3]));
        }
        mt0 = fmaxf(mt0, __shfl_xor_sync(0xffffffffu, mt0, 1));
        mt0 = fmaxf(mt0, __shfl_xor_sync(0xffffffffu, mt0, 2));
        mt1 = fmaxf(mt1, __shfl_xor_sync(0xffffffffu, mt1, 1));
        mt1 = fmaxf(mt1, __shfl_xor_sync(0xffffffffu, mt1, 2));

        float mn0 = fmaxf(m0, mt0), mn1 = fmaxf(m1, mt1);
        float c0 = __expf(m0 - mn0), c1 = __expf(m1 - mn1);
        m0 = mn0; m1 = mn1;

        // ---- exp, row sums, write P (tf32) to per-warp smem tile ----
        float rs0 = 0.f, rs1 = 0.f;
        #pragma unroll
        for (int ni = 0; ni < 16; ni++) {
            float p0 = __expf(s[ni][0] - m0);
            float p1 = __expf(s[ni][1] - m0);
            float p2 = __expf(s[ni][2] - m1);
            float p3 = __expf(s[ni][3] - m1);
            rs0 += p0 + p1;
            rs1 += p2 + p3;
            int row = wm + g;
            int col = ni*8 + 2*t;
            Ps[row*PSP + col]       = f2tf(p0);
            Ps[row*PSP + col + 1]   = f2tf(p1);
            Ps[(row+8)*PSP + col]   = f2tf(p2);
            Ps[(row+8)*PSP + col+1] = f2tf(p3);
        }
        rs0 += __shfl_xor_sync(0xffffffffu, rs0, 1);
        rs0 += __shfl_xor_sync(0xffffffffu, rs0, 2);
        rs1 += __shfl_xor_sync(0xffffffffu, rs1, 1);
        rs1 += __shfl_xor_sync(0xffffffffu, rs1, 2);
        l0 = l0 * c0 + rs0;
        l1 = l1 * c1 + rs1;

        // rescale O accumulator
        #pragma unroll
        for (int oni = 0; oni < 8; oni++) {
            o[oni][0] *= c0; o[oni][1] *= c0;
            o[oni][2] *= c1; o[oni][3] *= c1;
        }

        __syncwarp();

        // ---- O += P V : k over 128 keys ----
        #pragma unroll
        for (int kk = 0; kk < 16; kk++) {
            unsigned a0 = Ps[(wm + g)*PSP     + kk*8 + t];
            unsigned a1 = Ps[(wm + 8 + g)*PSP + kk*8 + t];
            unsigned a2 = Ps[(wm + g)*PSP     + kk*8 + 4 + t];
            unsigned a3 = Ps[(wm + 8 + g)*PSP + kk*8 + 4 + t];
            #pragma unroll
            for (int oni = 0; oni < 8; oni++) {
                unsigned b0 = f2tf(Vtile[(kk*8 + t)*VSP     + oni*8 + g]);
                unsigned b1 = f2tf(Vtile[(kk*8 + 4 + t)*VSP + oni*8 + g]);
                mma8(o[oni], a0, a1, a2, a3, b0, b1);
            }
        }
        __syncthreads();
    }

    // ---- epilogue: divide by l, write ctx ----
    float i0 = 1.f / l0, i1 = 1.f / l1;
    int r0 = qBase + wm + g, r1 = r0 + 8;
    #pragma unroll
    for (int oni = 0; oni < 8; oni++) {
        int c = oni*8 + 2*t;
        float2 v0 = make_float2(o[oni][0] * i0, o[oni][1] * i0);
        float2 v1 = make_float2(o[oni][2] * i1, o[oni][3] * i1);
        *(float2*)&Cg[(size_t)r0*Hd + c] = v0;
        *(float2*)&Cg[(size_t)r1*Hd + c] = v1;
    }
}

// ---------------- launch ----------------
extern "C" void kernel_launch(void* const* d_in, const int* in_sizes, int n_in,
                              void* d_out, int out_size)
{
    const int*           src  = (const int*)d_in[0];
    const unsigned char* mask = (const unsigned char*)d_in[1];
    const float* emb  = (const float*)d_in[2];
    const float* Wq   = (const float*)d_in[3];
    const float* bq   = (const float*)d_in[4];
    const float* Wk   = (const float*)d_in[5];
    const float* bk   = (const float*)d_in[6];
    const float* Wv   = (const float*)d_in[7];
    const float* bv   = (const float*)d_in[8];
    const float* Wo   = (const float*)d_in[9];
    const float* bo   = (const float*)d_in[10];
    const float* ln1g = (const float*)d_in[11];
    const float* ln1b = (const float*)d_in[12];
    const float* W1   = (const float*)d_in[13];
    const float* b1   = (const float*)d_in[14];
    const float* W2   = (const float*)d_in[15];
    const float* b2   = (const float*)d_in[16];
    const float* ln2g = (const float*)d_in[17];
    const float* ln2b = (const float*)d_in[18];
    const float* lnfg = (const float*)d_in[19];
    const float* lnfb = (const float*)d_in[20];
    const float* Wg   = (const float*)d_in[21];
    const float* bg   = (const float*)d_in[22];
    float* out = (float*)d_out;

    float *x, *h, *q, *k, *v, *ctx, *ff;
    cudaGetSymbolAddress((void**)&x,   g_x);
    cudaGetSymbolAddress((void**)&h,   g_h);
    cudaGetSymbolAddress((void**)&q,   g_q);
    cudaGetSymbolAddress((void**)&k,   g_k);
    cudaGetSymbolAddress((void**)&v,   g_v);
    cudaGetSymbolAddress((void**)&ctx, g_ctx);
    cudaGetSymbolAddress((void**)&ff,  g_ff);

    static bool attr_set = false;
    if (!attr_set) {
        cudaFuncSetAttribute(flash_attn,
                             cudaFuncAttributeMaxDynamicSharedMemorySize, FLASH_SMEM);
        attr_set = true;
    }

    embed_kernel<<<(Nt*Hd + 255)/256, 256>>>(src, emb, x);

    dim3 gH(Hd/128,  Nt/128);
    dim3 gF(FFd/128, Nt/128);
    dim3 gV((Vocab+127)/128, Nt/128);

    for (int l = 0; l < Lx; l++) {
        layernorm_kernel<<<Nt, 128>>>(x, ln1g + (size_t)l*Hd, ln1b + (size_t)l*Hd, h);

        gemm_tf32<false,false><<<gH, 256>>>(h, Wq + (size_t)l*Hd*Hd, bq + (size_t)l*Hd,
                                            nullptr, q, Nt, Hd, Hd);
        gemm_tf32<false,false><<<gH, 256>>>(h, Wk + (size_t)l*Hd*Hd, bk + (size_t)l*Hd,
                                            nullptr, k, Nt, Hd, Hd);
        gemm_tf32<false,false><<<gH, 256>>>(h, Wv + (size_t)l*Hd*Hd, bv + (size_t)l*Hd,
                                            nullptr, v, Nt, Hd, Hd);

        flash_attn<<<dim3(Sd/128, Bd*NHd), 256, FLASH_SMEM>>>(q, k, v, mask, ctx);

        // x = x + ctx @ Wo + bo
        gemm_tf32<false,true><<<gH, 256>>>(ctx, Wo + (size_t)l*Hd*Hd, bo + (size_t)l*Hd,
                                           x, x, Nt, Hd, Hd);

        layernorm_kernel<<<Nt, 128>>>(x, ln2g + (size_t)l*Hd, ln2b + (size_t)l*Hd, h);

        // ff = relu(h @ W1 + b1)
        gemm_tf32<true,false><<<gF, 256>>>(h, W1 + (size_t)l*Hd*FFd, b1 + (size_t)l*FFd,
                                           nullptr, ff, Nt, FFd, Hd);
        // x = x + ff @ W2 + b2
        gemm_tf32<false,true><<<gH, 256>>>(ff, W2 + (size_t)l*FFd*Hd, b2 + (size_t)l*Hd,
                                           x, x, Nt, Hd, FFd);
    }

    layernorm_kernel<<<Nt, 128>>>(x, lnfg, lnfb, h);
    gemm_tf32<false,false><<<gV, 256>>>(h, Wg, bg, nullptr, out, Nt, Vocab, Hd);
}